// round 14
// baseline (speedup 1.0000x reference)
#include <cuda_runtime.h>
#include <cuda_fp16.h>
#include <cfloat>
#include <cstdint>

// Problem constants
#define NITEMS 2
#define CCH 64
#define HH 96
#define WW 96
#define HP 94
#define WP 94
#define MM (HP*WP)          // 8836 patches per item
#define SY 24               // patch rows per strip block
#define NSTRIP 4
#define NDY 187             // Dy in [-93, 93]
#define VST 100             // Vp plane row stride (floats): deg-2 STS.64 banks
#define PLANE (HH*VST)      // 9600 floats per V plane
#define NTHR 384            // 12 warps, grid 3m x 4n, warp tile m32 x n24
#define XH 136              // halves per x-row in smem (128 data + 8 pad = 272B)
#define SLABH (WW*XH)       // 13056 halves per slab (26112B)
#define GROWH (WW*128)      // 12288 halves per row slab in gmem (hi64|lo64 per x)

// Static device scratch (allocation-free rule)
__device__ __half g_featp[2][NITEMS][HH][GROWH];          // [t][n][row][x: hi(64)|lo(64)]
__device__ unsigned long long g_best64[NITEMS][MM];       // packed (value, ~r)

__device__ __forceinline__ unsigned su(const void* p) {
    return (unsigned)__cvta_generic_to_shared(p);
}

__device__ __forceinline__ unsigned long long packkey(float v, int r) {
    unsigned u = __float_as_uint(v);
    u = (u & 0x80000000u) ? ~u : (u | 0x80000000u);   // monotone float -> uint
    return ((unsigned long long)u << 32) | (unsigned)(~r);  // bigger = better; tie -> smaller r
}

__device__ __forceinline__ void ldsm4(uint32_t& r0, uint32_t& r1, uint32_t& r2, uint32_t& r3,
                                      unsigned a) {
    asm volatile("ldmatrix.sync.aligned.m8n8.x4.shared.b16 {%0,%1,%2,%3}, [%4];"
        : "=r"(r0), "=r"(r1), "=r"(r2), "=r"(r3) : "r"(a));
}
__device__ __forceinline__ void ldsm2(uint32_t& r0, uint32_t& r1, unsigned a) {
    asm volatile("ldmatrix.sync.aligned.m8n8.x2.shared.b16 {%0,%1}, [%2];"
        : "=r"(r0), "=r"(r1) : "r"(a));
}
__device__ __forceinline__ void mma16(float* c, const uint32_t* a, uint32_t b0, uint32_t b1) {
    asm volatile("mma.sync.aligned.m16n8k16.row.col.f32.f16.f16.f32 "
        "{%0,%1,%2,%3}, {%4,%5,%6,%7}, {%8,%9}, {%0,%1,%2,%3};"
        : "+f"(c[0]), "+f"(c[1]), "+f"(c[2]), "+f"(c[3])
        : "r"(a[0]), "r"(a[1]), "r"(a[2]), "r"(a[3]), "r"(b0), "r"(b1));
}

// ---------------------------------------------------------------------------
// Kernel 1: per-pixel channel L2 normalization, fp32 NCHW -> fp16 hi/lo split
// Row slab layout: per x, 64 hi halves then 64 lo halves (256B per x).
// ---------------------------------------------------------------------------
__global__ void normalize_kernel(const float* __restrict__ f1,
                                 const float* __restrict__ f2) {
    __shared__ float tile[CCH][WW + 1];
    __shared__ float scale[WW];
    int row = blockIdx.x, t = blockIdx.y, n = blockIdx.z;
    const float* src = (t == 0 ? f1 : f2) + (size_t)n * CCH * HH * WW + (size_t)row * WW;

    for (int j = threadIdx.x; j < CCH * WW; j += 256) {
        int c = j / WW, x = j % WW;
        tile[c][x] = src[(size_t)c * HH * WW + x];
    }
    __syncthreads();
    if (threadIdx.x < WW) {
        float ss = 0.f;
        #pragma unroll
        for (int c = 0; c < CCH; c++) { float v = tile[c][threadIdx.x]; ss += v * v; }
        scale[threadIdx.x] = 1.0f / fmaxf(sqrtf(ss), 1e-12f);
    }
    __syncthreads();
    __half* dst = g_featp[t][n][row];
    for (int j = threadIdx.x; j < CCH * WW; j += 256) {
        int x = j >> 6, c = j & 63;
        float v = tile[c][x] * scale[x];
        __half hi = __float2half_rn(v);
        __half lo = __float2half_rn(v - __half2float(hi));
        dst[x * 128 + c] = hi;
        dst[x * 128 + 64 + c] = lo;
    }
}

// ---------------------------------------------------------------------------
// Kernel 2: reset argmax state (required every graph replay)
// ---------------------------------------------------------------------------
__global__ void init_kernel() {
    int i = blockIdx.x * 256 + threadIdx.x;
    if (i < NITEMS * MM) ((unsigned long long*)g_best64)[i] = 0ull;
}

// ---------------------------------------------------------------------------
// Kernel 3: displacement-decomposed correlation + argmax, 384 threads.
// Warp grid (3m x 4n), warp tile m32 x n24 -> ldsm crossbar traffic 245->172KB
// per row-iter. Software-pipelined: GEMM row k, emit V(row k-2) -> plane[k&1],
// argmax V(row k-3) from plane[(k&1)^1]; one __syncthreads per iteration.
// ---------------------------------------------------------------------------
__device__ __forceinline__ void load_rows(const __half* fa, const __half* fb,
                                          __half* da, __half* db, int tid) {
    #pragma unroll
    for (int q = 0; q < 8; q++) {
        int idx = tid + NTHR * q;          // 0..3071
        int tsel = idx >= 1536;
        int g = idx - 1536 * tsel;
        int x = g >> 4, seg = g & 15;
        const __half* sp = (tsel ? fb : fa) + g * 8;
        __half* dp = (tsel ? db : da) + x * XH + seg * 8;
        unsigned d = su(dp);
        asm volatile("cp.async.cg.shared.global [%0], [%1], 16;\n" :: "r"(d), "l"(sp));
    }
    asm volatile("cp.async.commit_group;\n" ::: "memory");
}

__global__ __launch_bounds__(NTHR, 1)
void corr_kernel() {
    extern __shared__ __align__(16) char smraw[];
    __half* smH = (__half*)smraw;                       // 4 slabs: [buf][A,B]
    float* VpBase = (float*)(smraw + 4 * SLABH * 2);    // 2 planes of PLANE floats

    const int d = blockIdx.x >> 2;         // 0..186
    const int s = blockIdx.x & 3;
    const int Dy = d - 93;
    const int item = blockIdx.y;
    const int ylo = Dy < 0 ? -Dy : 0;
    const int yhi = HP - (Dy > 0 ? Dy : 0);
    const int y0 = ylo + s * SY;
    if (y0 >= yhi) return;
    int rows = yhi - y0; if (rows > SY) rows = SY;

    const int tid = threadIdx.x;
    const int lane = tid & 31;
    const int w = tid >> 5;                // 0..11
    const int m0 = (w % 3) * 32;           // m-tile base (x), 32 rows
    const int nb = (w / 3) * 24;           // n base (xr), 3 tiles of 8

    const __half* finBase  = g_featp[0][item][0];
    const __half* frefBase = g_featp[1][item][0];

    // ldmatrix per-lane byte offsets (within a slab)
    const int lm = lane >> 3, lr = lane & 7;
    const int aOff0 = ((m0 + lr + 8 * (lm & 1)) * XH + 8 * (lm >> 1)) * 2;   // m16 tile 0
    const int aOff1 = aOff0 + 16 * XH * 2;                                    // m16 tile 1
    const int bOffBase = ((nb + lr) * XH) * 2;
    const int bK = ((lm & 1) * 8) * 2;

    // emit addressing (fragment -> plane)
    const int eRow = m0 + (lane >> 2);
    const int eCol = nb + (lane & 3) * 2;

    float acc[2][3][4], S1[2][3][4], S2[2][3][4];
    #pragma unroll
    for (int mf = 0; mf < 2; mf++)
        #pragma unroll
        for (int t = 0; t < 3; t++)
            #pragma unroll
            for (int p = 0; p < 4; p++) { S1[mf][t][p] = 0.f; S2[mf][t][p] = 0.f; }

    load_rows(finBase + (size_t)y0 * GROWH, frefBase + (size_t)(y0 + Dy) * GROWH,
              smH, smH + SLABH, tid);

    for (int k = 0; k < rows + 3; k++) {
        const int buf = k & 1;
        asm volatile("cp.async.wait_group 0;\n" ::: "memory");
        __syncthreads();   // slab ready + Vp plane handoff
        if (k + 1 < rows + 2) {
            int p = y0 + k + 1;
            load_rows(finBase + (size_t)p * GROWH, frefBase + (size_t)(p + Dy) * GROWH,
                      smH + (buf ^ 1) * 2 * SLABH, smH + (buf ^ 1) * 2 * SLABH + SLABH, tid);
        }

        if (k < rows + 2) {
            const __half* As = smH + buf * 2 * SLABH;
            const __half* Bs = As + SLABH;

            #pragma unroll
            for (int mf = 0; mf < 2; mf++)
                #pragma unroll
                for (int t = 0; t < 3; t++)
                    #pragma unroll
                    for (int p = 0; p < 4; p++) acc[mf][t][p] = 0.f;

            // ---- rowdot GEMM: 4 ksteps of 16 channels, fp16 hi/lo 3-pass ----
            #pragma unroll
            for (int ks = 0; ks < 4; ks++) {
                uint32_t ah[2][4], al[2][4];
                unsigned ab0 = su((const char*)As + aOff0 + ks * 32);
                ldsm4(ah[0][0], ah[0][1], ah[0][2], ah[0][3], ab0);
                ldsm4(al[0][0], al[0][1], al[0][2], al[0][3], ab0 + 128);
                unsigned ab1 = su((const char*)As + aOff1 + ks * 32);
                ldsm4(ah[1][0], ah[1][1], ah[1][2], ah[1][3], ab1);
                ldsm4(al[1][0], al[1][1], al[1][2], al[1][3], ab1 + 128);
                #pragma unroll
                for (int t = 0; t < 3; t++) {
                    uint32_t bh0, bh1, bl0, bl1;
                    unsigned bbase = su((const char*)Bs + bOffBase + t * (8 * XH * 2) + bK + ks * 32);
                    ldsm2(bh0, bh1, bbase);
                    ldsm2(bl0, bl1, bbase + 128);
                    #pragma unroll
                    for (int mf = 0; mf < 2; mf++) {
                        mma16(acc[mf][t], ah[mf], bh0, bh1);   // hi*hi
                        mma16(acc[mf][t], ah[mf], bl0, bl1);   // hi*lo
                        mma16(acc[mf][t], al[mf], bh0, bh1);   // lo*hi
                    }
                }
            }

            // ---- vertical running sums in regs; V -> plane[k&1] via STS.64 ----
            const bool emit = (k >= 2);
            float* plane = VpBase + buf * PLANE;
            #pragma unroll
            for (int mf = 0; mf < 2; mf++) {
                #pragma unroll
                for (int t = 0; t < 3; t++) {
                    #pragma unroll
                    for (int ph = 0; ph < 2; ph++) {
                        float r0 = acc[mf][t][2 * ph], r1 = acc[mf][t][2 * ph + 1];
                        if (emit) {
                            float2 e = make_float2(S2[mf][t][2 * ph] + r0,
                                                   S2[mf][t][2 * ph + 1] + r1);
                            *(float2*)(plane + (eRow + 16 * mf + 8 * ph) * VST + eCol + t * 8) = e;
                        }
                        S2[mf][t][2 * ph]     = S1[mf][t][2 * ph]     + r0;
                        S2[mf][t][2 * ph + 1] = S1[mf][t][2 * ph + 1] + r1;
                        S1[mf][t][2 * ph]     = r0;
                        S1[mf][t][2 * ph + 1] = r1;
                    }
                }
            }
        }

        // ---- argmax over V(row y0+k-3) from plane[(k&1)^1] ----
        if (k >= 3) {
            const float* plane = VpBase + (buf ^ 1) * PLANE;
            const int y = y0 + k - 3;
            const int ry = y + Dy;
            #pragma unroll
            for (int i = 0; i < 8; i++) {
                int xx = w + 12 * i;
                float bv = -FLT_MAX; int brx = 0;
                if (xx < HP) {
                    const float* v0 = plane + xx * VST;
                    #pragma unroll
                    for (int j = 0; j < 3; j++) {
                        int rx = lane + 32 * j;
                        if (rx < HP) {
                            float v = v0[rx] + v0[VST + 1 + rx] + v0[2 * VST + 2 + rx];
                            if (v > bv) { bv = v; brx = rx; }
                        }
                    }
                }
                #pragma unroll
                for (int off = 16; off >= 1; off >>= 1) {
                    float ov = __shfl_down_sync(0xffffffffu, bv, off);
                    int orx = __shfl_down_sync(0xffffffffu, brx, off);
                    if (ov > bv || (ov == bv && orx < brx)) { bv = ov; brx = orx; }
                }
                if (lane == 0 && xx < HP) {
                    atomicMax(&g_best64[item][y * WP + xx], packkey(bv, ry * WP + brx));
                }
            }
        }
    }
}

// ---------------------------------------------------------------------------
// Kernel 4: decode best index -> flow -> shift -> reorder. out (N,18,H,W) f32
// ---------------------------------------------------------------------------
__global__ void epilogue_kernel(float* __restrict__ out) {
    int i = blockIdx.x * 256 + threadIdx.x;
    const int total = NITEMS * 18 * HH * WW;
    if (i >= total) return;
    int w = i % WW;
    int h = (i / WW) % HH;
    int ch = (i / (WW * HH)) % 18;
    int n = i / (WW * HH * 18);
    int s = ch >> 1, comp = ch & 1;
    int si = s / 3, sj = s % 3;
    int y = h - si, x = w - sj;
    float val = 0.f;
    if (y >= 0 && y < HP && x >= 0 && x < WP) {
        unsigned long long key = g_best64[n][y * WP + x];
        int idx = (int)(~(unsigned)(key & 0xffffffffull));
        val = (comp == 0) ? (float)(idx / WP - y) : (float)(idx % WP - x);
    }
    out[i] = val;
}

// ---------------------------------------------------------------------------
extern "C" void kernel_launch(void* const* d_in, const int* in_sizes, int n_in,
                              void* d_out, int out_size) {
    const float* f1 = (const float*)d_in[0];
    const float* f2 = (const float*)d_in[1];

    const int smem_bytes = 4 * SLABH * 2 + 2 * PLANE * 4;   // 104448 + 76800 = 181248
    cudaFuncSetAttribute(corr_kernel,
                         cudaFuncAttributeMaxDynamicSharedMemorySize, smem_bytes);

    normalize_kernel<<<dim3(HH, 2, NITEMS), 256>>>(f1, f2);
    init_kernel<<<(NITEMS * MM + 255) / 256, 256>>>();
    corr_kernel<<<dim3(NDY * NSTRIP, NITEMS), NTHR, smem_bytes>>>();
    int total = NITEMS * 18 * HH * WW;
    epilogue_kernel<<<(total + 255) / 256, 256>>>((float*)d_out);
}